// round 14
// baseline (speedup 1.0000x reference)
#include <cuda_runtime.h>

#define T_DIM 1024
#define F_DIM 256
#define F4    (F_DIM / 4)
#define F2    (F_DIM / 2)
#define UNITS 32
#define AW    64
#define HALF  32
#define B_DIM 4
#define NROWS (B_DIM * T_DIM)
#define AP    72            // padded weight stride: zeros [0..2], data [3..66], zeros [67..71]
#define TT    16            // attn t-tile

typedef unsigned long long u64;

__device__ float g_q[NROWS * UNITS];
__device__ float g_k[NROWS * UNITS];

__device__ __forceinline__ float tanh_approx(float x) {
    float y;
    asm("tanh.approx.f32 %0, %1;" : "=f"(y) : "f"(x));
    return y;
}
__device__ __forceinline__ u64 ffma2(u64 a, u64 b, u64 c) {
    u64 d;
    asm("fma.rn.f32x2 %0, %1, %2, %3;" : "=l"(d) : "l"(a), "l"(b), "l"(c));
    return d;
}
__device__ __forceinline__ u64 addx2(u64 a, u64 b) {
    u64 d;
    asm("add.rn.f32x2 %0, %1, %2;" : "=l"(d) : "l"(a), "l"(b));
    return d;
}
__device__ __forceinline__ u64 dup2(float w) {
    u64 d;
    asm("mov.b64 %0, {%1, %1};" : "=l"(d) : "f"(w));
    return d;
}
__device__ __forceinline__ void f4_to_u64(float4 v, u64& a, u64& b) {
    asm("mov.b64 %0, {%2, %3};\n\tmov.b64 %1, {%4, %5};"
        : "=l"(a), "=l"(b) : "f"(v.x), "f"(v.y), "f"(v.z), "f"(v.w));
}
__device__ __forceinline__ void u64_to_f4(u64 a, u64 b, float4& v) {
    asm("mov.b64 {%0, %1}, %4;\n\tmov.b64 {%2, %3}, %5;"
        : "=f"(v.x), "=f"(v.y), "=f"(v.z), "=f"(v.w) : "l"(a), "l"(b));
}
__device__ __forceinline__ u64 shfl_xor_u64(u64 v, int m) {
    double d = __longlong_as_double((long long)v);
    d = __shfl_xor_sync(0xffffffffu, d, m);
    return (u64)__double_as_longlong(d);
}

// ---------------------------------------------------------------------------
// Kernel 1 (R13 version): q = x@Wt + bh, k = x@Wx. Transposed-W, 2 rows/warp,
// 512 blocks, launch_bounds(256,3) for deeper LDG pipelining.
// ---------------------------------------------------------------------------
__global__ void __launch_bounds__(256, 3) qk_kernel(
    const float* __restrict__ x,
    const float* __restrict__ Wt,
    const float* __restrict__ Wx,
    const float* __restrict__ bh)
{
    __shared__ float xs[8 * F_DIM];                  // 8 rows = 8KB

    const int tid = threadIdx.x;
    const int r0  = blockIdx.x * 8;

    const float4* xg  = reinterpret_cast<const float4*>(x) + (size_t)r0 * F4;
    float4*       xs4 = reinterpret_cast<float4*>(xs);
    xs4[tid]       = xg[tid];
    xs4[tid + 256] = xg[tid + 256];
    __syncthreads();

    const int  wid  = tid >> 5;
    const int  lane = tid & 31;
    const bool is_q = (wid < 4);
    const int  rp   = wid & 3;                       // row pair
    const int  fg   = lane >> 3;                     // f-subgroup 0..3
    const int  u4   = lane & 7;                      // unit quad 0..7

    const float4* __restrict__ Wf4 =
        reinterpret_cast<const float4*>(is_q ? Wt : Wx);   // [F][8 quads]
    const float* xr0 = xs + (2 * rp + 0) * F_DIM;
    const float* xr1 = xs + (2 * rp + 1) * F_DIM;

    u64 a0 = 0ull, b0 = 0ull, a1 = 0ull, b1 = 0ull;

    #pragma unroll 8
    for (int c = 0; c < 64; c++) {                   // lane's f = 4c + fg
        const float4 wv = Wf4[32 * c + lane];        // LDG.128, coalesced
        u64 w01, w23;
        f4_to_u64(wv, w01, w23);
        const u64 xv0 = dup2(xr0[4 * c + fg]);       // LDS.32 broadcast
        const u64 xv1 = dup2(xr1[4 * c + fg]);
        a0 = ffma2(xv0, w01, a0);  b0 = ffma2(xv0, w23, b0);
        a1 = ffma2(xv1, w01, a1);  b1 = ffma2(xv1, w23, b1);
    }

    a0 = addx2(a0, shfl_xor_u64(a0, 8));  a0 = addx2(a0, shfl_xor_u64(a0, 16));
    b0 = addx2(b0, shfl_xor_u64(b0, 8));  b0 = addx2(b0, shfl_xor_u64(b0, 16));
    a1 = addx2(a1, shfl_xor_u64(a1, 8));  a1 = addx2(a1, shfl_xor_u64(a1, 16));
    b1 = addx2(b1, shfl_xor_u64(b1, 8));  b1 = addx2(b1, shfl_xor_u64(b1, 16));

    if (fg < 2) {                                    // fg 0 -> row0, fg 1 -> row1
        const u64 wa = fg ? a1 : a0;
        const u64 wb = fg ? b1 : b0;
        float4 o;
        u64_to_f4(wa, wb, o);
        if (is_q) {
            const float4 bv = reinterpret_cast<const float4*>(bh)[u4];
            o.x += bv.x; o.y += bv.y; o.z += bv.z; o.w += bv.w;
        }
        float4* __restrict__ G4 =
            reinterpret_cast<float4*>(is_q ? g_q : g_k);
        G4[(size_t)(r0 + 2 * rp + fg) * 8 + u4] = o; // STG.128
    }
}

// ---------------------------------------------------------------------------
// Kernel 2 (fused): logits + softmax + v = a @ x for a 16-t tile.
// grid (T/16, B) = 256 blocks, 512 threads (16 warps), all warps active in
// every phase. Phase D: warp = (t-quad, f-quarter), lane owns one float2;
// 4-t x-reuse halves L1 wavefront traffic vs the 2-t version.
// ---------------------------------------------------------------------------
__global__ void __launch_bounds__(512) attn_out_kernel(
    const float* __restrict__ x,
    const float* __restrict__ Wa,
    const float* __restrict__ ba,
    float* __restrict__ out)
{
    const int b  = blockIdx.y;
    const int t0 = blockIdx.x * TT;
    const int sbase = t0 - HALF;
    const int SR = TT + AW - 1;                  // 79 staged k rows

    __shared__ float ks[79 * 33];                // padded, conflict-free
    __shared__ float qs[TT * UNITS];
    __shared__ float was[UNITS];
    __shared__ float es[TT * AW];
    __shared__ float asf[TT * AP];               // scalar weights, zero-padded

    const int tid = threadIdx.x;

    for (int idx = tid; idx < SR * UNITS; idx += 512) {
        const int srel = idx >> 5, u = idx & 31;
        int s = sbase + srel;
        s = min(max(s, 0), T_DIM - 1);           // OOB rows masked via es
        ks[srel * 33 + u] = g_k[(size_t)(b * T_DIM + s) * UNITS + u];
    }
    qs[tid] = g_q[(size_t)(b * T_DIM + t0) * UNITS + tid];   // 512 = TT*UNITS
    if (tid < UNITS) was[tid] = Wa[tid];
    __syncthreads();

    // --- logits: 2 per thread (16 t x 64 j = 1024) -------------------------
    #pragma unroll
    for (int l = 0; l < 2; l++) {
        const int idx = tid + l * 512;
        const int tl  = idx >> 6;
        const int j   = idx & 63;
        const int s   = t0 + tl - HALF + j;
        float e = -1e30f;
        if (s >= 0 && s < T_DIM) {
            const int srel = tl + j;
            float acc = 0.f;
            #pragma unroll
            for (int u = 0; u < UNITS; u++)
                acc += was[u] * tanh_approx(qs[tl * UNITS + u] + ks[srel * 33 + u]);
            e = acc + ba[0];
        }
        es[tl * AW + j] = e;
    }
    __syncthreads();

    // --- softmax: 16 warps, one t-row each; write zero-padded scalars ------
    const int wid = tid >> 5, lane = tid & 31;
    {
        const float e0 = es[wid * AW + lane];
        const float e1 = es[wid * AW + lane + 32];
        float m = fmaxf(e0, e1);
        #pragma unroll
        for (int o = 16; o; o >>= 1)
            m = fmaxf(m, __shfl_xor_sync(0xffffffffu, m, o));
        const float p0 = __expf(e0 - m);
        const float p1 = __expf(e1 - m);
        float sum = p0 + p1;
        #pragma unroll
        for (int o = 16; o; o >>= 1)
            sum += __shfl_xor_sync(0xffffffffu, sum, o);
        const float inv = 1.f / sum;
        asf[wid * AP + 3 + lane]  = p0 * inv;    // exactly 0 when masked
        asf[wid * AP + 35 + lane] = p1 * inv;
        if (lane < 3) asf[wid * AP + lane]      = 0.f;   // left pad
        if (lane < 5) asf[wid * AP + 67 + lane] = 0.f;   // right pad
    }
    __syncthreads();

    // --- phase D: all 16 warps = (t-quad 0..3, f-quarter 0..3) -------------
    const int qd = wid & 3;                      // t-quad
    const int fq = wid >> 2;                     // f-quarter
    const int f2 = fq * 32 + lane;               // float2 column (128 per row)
    const int tq = t0 + 4 * qd;

    const u64* __restrict__ xg2 =
        reinterpret_cast<const u64*>(x) + (size_t)b * T_DIM * F2;
    // row r weight for window index i is asf[(4qd+r)*AP + 3 + i - r]
    const float* aw0 = asf + (4 * qd + 0) * AP + 3;
    const float* aw1 = asf + (4 * qd + 1) * AP + 2;
    const float* aw2 = asf + (4 * qd + 2) * AP + 1;
    const float* aw3 = asf + (4 * qd + 3) * AP + 0;

    u64 a0 = 0ull, a1 = 0ull, a2 = 0ull, a3 = 0ull;

    if (t0 >= HALF && t0 + 46 < T_DIM) {
        // ---- interior: pointer walk, no clamps ----
        const u64* xp = xg2 + (size_t)(tq - HALF) * F2 + f2;
        #pragma unroll 4
        for (int i = 0; i < AW + 3; i++) {       // 67-row union window
            const u64 xv = *xp;                  // LDG.64
            xp += F2;
            a0 = ffma2(xv, dup2(aw0[i]), a0);    // LDS.32 bcast + mov
            a1 = ffma2(xv, dup2(aw1[i]), a1);
            a2 = ffma2(xv, dup2(aw2[i]), a2);
            a3 = ffma2(xv, dup2(aw3[i]), a3);
        }
    } else {
        #pragma unroll 4
        for (int i = 0; i < AW + 3; i++) {
            int s = tq - HALF + i;
            s = min(max(s, 0), T_DIM - 1);       // weight is 0 when OOB
            const u64 xv = xg2[(size_t)s * F2 + f2];
            a0 = ffma2(xv, dup2(aw0[i]), a0);
            a1 = ffma2(xv, dup2(aw1[i]), a1);
            a2 = ffma2(xv, dup2(aw2[i]), a2);
            a3 = ffma2(xv, dup2(aw3[i]), a3);
        }
    }

    u64* __restrict__ og2 =
        reinterpret_cast<u64*>(out) + (size_t)b * T_DIM * F2;
    og2[(size_t)(tq + 0) * F2 + f2] = a0;        // STG.64
    og2[(size_t)(tq + 1) * F2 + f2] = a1;
    og2[(size_t)(tq + 2) * F2 + f2] = a2;
    og2[(size_t)(tq + 3) * F2 + f2] = a3;
}

extern "C" void kernel_launch(void* const* d_in, const int* in_sizes, int n_in,
                              void* d_out, int out_size)
{
    const float* x  = (const float*)d_in[0];
    const float* Wt = (const float*)d_in[1];
    const float* Wx = (const float*)d_in[2];
    const float* bh = (const float*)d_in[3];
    const float* Wa = (const float*)d_in[4];
    const float* ba = (const float*)d_in[5];
    float* out = (float*)d_out;

    qk_kernel<<<NROWS / 8, 256>>>(x, Wt, Wx, bh);
    attn_out_kernel<<<dim3(T_DIM / TT, B_DIM), 512>>>(x, Wa, ba, out);
}

// round 15
// speedup vs baseline: 1.0837x; 1.0837x over previous
#include <cuda_runtime.h>

#define T_DIM 1024
#define F_DIM 256
#define F4    (F_DIM / 4)
#define UNITS 32
#define AW    64
#define HALF  32
#define B_DIM 4
#define NROWS (B_DIM * T_DIM)
#define AP    66            // padded weight stride (zeros at [0] and [65])

typedef unsigned long long u64;

__device__ float g_q[NROWS * UNITS];
__device__ float g_k[NROWS * UNITS];

__device__ __forceinline__ float tanh_approx(float x) {
    float y;
    asm("tanh.approx.f32 %0, %1;" : "=f"(y) : "f"(x));
    return y;
}
__device__ __forceinline__ u64 ffma2(u64 a, u64 b, u64 c) {
    u64 d;
    asm("fma.rn.f32x2 %0, %1, %2, %3;" : "=l"(d) : "l"(a), "l"(b), "l"(c));
    return d;
}
__device__ __forceinline__ u64 addx2(u64 a, u64 b) {
    u64 d;
    asm("add.rn.f32x2 %0, %1, %2;" : "=l"(d) : "l"(a), "l"(b));
    return d;
}
__device__ __forceinline__ u64 pack2(float a, float b) {
    u64 d;
    asm("mov.b64 %0, {%1, %2};" : "=l"(d) : "f"(a), "f"(b));
    return d;
}
__device__ __forceinline__ u64 dup2(float w) {
    u64 d;
    asm("mov.b64 %0, {%1, %1};" : "=l"(d) : "f"(w));
    return d;
}
__device__ __forceinline__ void f4_to_u64(float4 v, u64& a, u64& b) {
    asm("mov.b64 %0, {%2, %3};\n\tmov.b64 %1, {%4, %5};"
        : "=l"(a), "=l"(b) : "f"(v.x), "f"(v.y), "f"(v.z), "f"(v.w));
}
__device__ __forceinline__ void u64_to_f4(u64 a, u64 b, float4& v) {
    asm("mov.b64 {%0, %1}, %4;\n\tmov.b64 {%2, %3}, %5;"
        : "=f"(v.x), "=f"(v.y), "=f"(v.z), "=f"(v.w) : "l"(a), "l"(b));
}
__device__ __forceinline__ u64 shfl_xor_u64(u64 v, int m) {
    double d = __longlong_as_double((long long)v);
    d = __shfl_xor_sync(0xffffffffu, d, m);
    return (u64)__double_as_longlong(d);
}

// ---------------------------------------------------------------------------
// Kernel 1 (R13 version): q = x@Wt + bh, k = x@Wx. Transposed-W, 2 rows/warp,
// 512 blocks, launch_bounds(256,3) for deeper LDG pipelining.
// ---------------------------------------------------------------------------
__global__ void __launch_bounds__(256, 3) qk_kernel(
    const float* __restrict__ x,
    const float* __restrict__ Wt,
    const float* __restrict__ Wx,
    const float* __restrict__ bh)
{
    __shared__ float xs[8 * F_DIM];                  // 8 rows = 8KB

    const int tid = threadIdx.x;
    const int r0  = blockIdx.x * 8;

    const float4* xg  = reinterpret_cast<const float4*>(x) + (size_t)r0 * F4;
    float4*       xs4 = reinterpret_cast<float4*>(xs);
    xs4[tid]       = xg[tid];
    xs4[tid + 256] = xg[tid + 256];
    __syncthreads();

    const int  wid  = tid >> 5;
    const int  lane = tid & 31;
    const bool is_q = (wid < 4);
    const int  rp   = wid & 3;                       // row pair
    const int  fg   = lane >> 3;                     // f-subgroup 0..3
    const int  u4   = lane & 7;                      // unit quad 0..7

    const float4* __restrict__ Wf4 =
        reinterpret_cast<const float4*>(is_q ? Wt : Wx);   // [F][8 quads]
    const float* xr0 = xs + (2 * rp + 0) * F_DIM;
    const float* xr1 = xs + (2 * rp + 1) * F_DIM;

    u64 a0 = 0ull, b0 = 0ull, a1 = 0ull, b1 = 0ull;

    #pragma unroll 8
    for (int c = 0; c < 64; c++) {                   // lane's f = 4c + fg
        const float4 wv = Wf4[32 * c + lane];        // LDG.128, coalesced
        u64 w01, w23;
        f4_to_u64(wv, w01, w23);
        const u64 xv0 = dup2(xr0[4 * c + fg]);       // LDS.32 broadcast
        const u64 xv1 = dup2(xr1[4 * c + fg]);
        a0 = ffma2(xv0, w01, a0);  b0 = ffma2(xv0, w23, b0);
        a1 = ffma2(xv1, w01, a1);  b1 = ffma2(xv1, w23, b1);
    }

    a0 = addx2(a0, shfl_xor_u64(a0, 8));  a0 = addx2(a0, shfl_xor_u64(a0, 16));
    b0 = addx2(b0, shfl_xor_u64(b0, 8));  b0 = addx2(b0, shfl_xor_u64(b0, 16));
    a1 = addx2(a1, shfl_xor_u64(a1, 8));  a1 = addx2(a1, shfl_xor_u64(a1, 16));
    b1 = addx2(b1, shfl_xor_u64(b1, 8));  b1 = addx2(b1, shfl_xor_u64(b1, 16));

    if (fg < 2) {                                    // fg 0 -> row0, fg 1 -> row1
        const u64 wa = fg ? a1 : a0;
        const u64 wb = fg ? b1 : b0;
        float4 o;
        u64_to_f4(wa, wb, o);
        if (is_q) {
            const float4 bv = reinterpret_cast<const float4*>(bh)[u4];
            o.x += bv.x; o.y += bv.y; o.z += bv.z; o.w += bv.w;
        }
        float4* __restrict__ G4 =
            reinterpret_cast<float4*>(is_q ? g_q : g_k);
        G4[(size_t)(r0 + 2 * rp + fg) * 8 + u4] = o; // STG.128
    }
}

// ---------------------------------------------------------------------------
// Kernel 2 (R12 fused, + 2-deep prefetch pipeline in phase D):
// logits + softmax + v = a @ x for an 8-t tile. 512 blocks x 256 threads.
// ---------------------------------------------------------------------------
__global__ void __launch_bounds__(256, 3) attn_out_kernel(
    const float* __restrict__ x,
    const float* __restrict__ Wa,
    const float* __restrict__ ba,
    float* __restrict__ out)
{
    const int b  = blockIdx.y;
    const int t0 = blockIdx.x * 8;
    const int sbase = t0 - HALF;
    const int SR = 8 + AW - 1;                   // 71 staged k rows

    __shared__ float ks[71 * 33];                // padded, conflict-free
    __shared__ float qs[8 * UNITS];
    __shared__ float was[UNITS];
    __shared__ float es[8 * AW];
    __shared__ u64   as2[8 * AP];                // dup pairs, zeros at [0],[65]

    const int tid = threadIdx.x;

    for (int idx = tid; idx < SR * UNITS; idx += 256) {
        const int srel = idx >> 5, u = idx & 31;
        int s = sbase + srel;
        s = min(max(s, 0), T_DIM - 1);           // OOB rows masked via es
        ks[srel * 33 + u] = g_k[(size_t)(b * T_DIM + s) * UNITS + u];
    }
    if (tid < 8 * UNITS)
        qs[tid] = g_q[(size_t)(b * T_DIM + t0) * UNITS + tid];
    if (tid < UNITS) was[tid] = Wa[tid];
    __syncthreads();

    // --- logits: 2 per thread (8 t x 64 j = 512) ---------------------------
    #pragma unroll
    for (int l = 0; l < 2; l++) {
        const int idx = tid + l * 256;
        const int tl  = idx >> 6;
        const int j   = idx & 63;
        const int s   = t0 + tl - HALF + j;
        float e = -1e30f;
        if (s >= 0 && s < T_DIM) {
            const int srel = tl + j;
            float acc = 0.f;
            #pragma unroll
            for (int u = 0; u < UNITS; u++)
                acc += was[u] * tanh_approx(qs[tl * UNITS + u] + ks[srel * 33 + u]);
            e = acc + ba[0];
        }
        es[tl * AW + j] = e;
    }
    __syncthreads();

    // --- softmax: 8 warps, one t each; write zero-padded dup pairs ---------
    const int wid = tid >> 5, lane = tid & 31;
    {
        const float e0 = es[wid * AW + lane];
        const float e1 = es[wid * AW + lane + 32];
        float m = fmaxf(e0, e1);
        #pragma unroll
        for (int o = 16; o; o >>= 1)
            m = fmaxf(m, __shfl_xor_sync(0xffffffffu, m, o));
        const float p0 = __expf(e0 - m);
        const float p1 = __expf(e1 - m);
        float sum = p0 + p1;
        #pragma unroll
        for (int o = 16; o; o >>= 1)
            sum += __shfl_xor_sync(0xffffffffu, sum, o);
        const float inv = 1.f / sum;
        const float a0 = p0 * inv, a1 = p1 * inv;   // exactly 0 when masked
        as2[wid * AP + 1 + lane]      = pack2(a0, a0);
        as2[wid * AP + 33 + lane]     = pack2(a1, a1);
        if (lane == 0) {
            as2[wid * AP + 0]      = 0ull;          // pad left
            as2[wid * AP + AW + 1] = 0ull;          // pad right
        }
    }
    __syncthreads();

    // --- phase D: warp = (2 t, f-half). Union window 65 rows. --------------
    const int p  = wid & 3;                      // t pair: 2p, 2p+1
    const int h  = wid >> 2;
    const int f4 = h * 32 + lane;
    const int ta = t0 + 2 * p;

    const float4* __restrict__ xg4 =
        reinterpret_cast<const float4*>(x) + (size_t)b * T_DIM * F4;
    const u64* awa = as2 + (2 * p + 0) * AP;     // index [1+i]
    const u64* awb = as2 + (2 * p + 1) * AP;     // index [i]

    u64 acc0a = 0ull, acc0b = 0ull, acc1a = 0ull, acc1b = 0ull;

    if (t0 >= HALF && t0 + 7 + HALF < T_DIM) {
        // ---- interior: 2-deep software pipeline (row i+2 in flight) ----
        const float4* xp = xg4 + (size_t)(ta - HALF) * F4 + f4;
        u64 ca, cb, na, nb;
        f4_to_u64(xp[0],  ca, cb);               // row 0
        f4_to_u64(xp[F4], na, nb);               // row 1
        xp += 2 * F4;
        #pragma unroll 7
        for (int i = 0; i < AW - 1; i++) {       // i = 0..62
            u64 fa, fb;
            f4_to_u64(*xp, fa, fb);              // prefetch row i+2
            xp += F4;
            const u64 w0 = awa[i + 1];           // LDS.64 dup pair
            const u64 w1 = awb[i];
            acc0a = ffma2(ca, w0, acc0a);
            acc0b = ffma2(cb, w0, acc0b);
            acc1a = ffma2(ca, w1, acc1a);
            acc1b = ffma2(cb, w1, acc1b);
            ca = na; cb = nb;
            na = fa; nb = fb;
        }
        {   // i = 63 (row 63 = ca), i = 64 (row 64 = na)
            const u64 w0 = awa[64];
            const u64 w1 = awb[63];
            acc0a = ffma2(ca, w0, acc0a);
            acc0b = ffma2(cb, w0, acc0b);
            acc1a = ffma2(ca, w1, acc1a);
            acc1b = ffma2(cb, w1, acc1b);
            const u64 v0 = awa[65];              // zero pad
            const u64 v1 = awb[64];
            acc0a = ffma2(na, v0, acc0a);
            acc0b = ffma2(nb, v0, acc0b);
            acc1a = ffma2(na, v1, acc1a);
            acc1b = ffma2(nb, v1, acc1b);
        }
    } else {
        // ---- boundary path: clamp s; OOB weights are exactly 0 ----
        #pragma unroll 5
        for (int i = 0; i < AW + 1; i++) {
            int s = ta - HALF + i;
            s = min(max(s, 0), T_DIM - 1);
            u64 xa, xb;
            f4_to_u64(xg4[(size_t)s * F4 + f4], xa, xb);
            const u64 w0 = awa[i + 1];
            const u64 w1 = awb[i];
            acc0a = ffma2(xa, w0, acc0a);
            acc0b = ffma2(xb, w0, acc0b);
            acc1a = ffma2(xa, w1, acc1a);
            acc1b = ffma2(xb, w1, acc1b);
        }
    }

    float4 o0, o1;
    u64_to_f4(acc0a, acc0b, o0);
    u64_to_f4(acc1a, acc1b, o1);
    float4* __restrict__ og =
        reinterpret_cast<float4*>(out) + (size_t)b * T_DIM * F4;
    og[(size_t)(ta + 0) * F4 + f4] = o0;
    og[(size_t)(ta + 1) * F4 + f4] = o1;
}

extern "C" void kernel_launch(void* const* d_in, const int* in_sizes, int n_in,
                              void* d_out, int out_size)
{
    const float* x  = (const float*)d_in[0];
    const float* Wt = (const float*)d_in[1];
    const float* Wx = (const float*)d_in[2];
    const float* bh = (const float*)d_in[3];
    const float* Wa = (const float*)d_in[4];
    const float* ba = (const float*)d_in[5];
    float* out = (float*)d_out;

    qk_kernel<<<NROWS / 8, 256>>>(x, Wt, Wx, bh);
    attn_out_kernel<<<dim3(T_DIM / 8, B_DIM), 256>>>(x, Wa, ba, out);
}

// round 16
// speedup vs baseline: 1.0850x; 1.0012x over previous
#include <cuda_runtime.h>

#define T_DIM 1024
#define F_DIM 256
#define F4    (F_DIM / 4)
#define UNITS 32
#define AW    64
#define HALF  32
#define B_DIM 4
#define NROWS (B_DIM * T_DIM)
#define AP    66            // padded weight stride (zeros at [0] and [65])
#define TT    16            // attn t-tile

typedef unsigned long long u64;

__device__ float g_q[NROWS * UNITS];
__device__ float g_k[NROWS * UNITS];

__device__ __forceinline__ float tanh_approx(float x) {
    float y;
    asm("tanh.approx.f32 %0, %1;" : "=f"(y) : "f"(x));
    return y;
}
__device__ __forceinline__ u64 ffma2(u64 a, u64 b, u64 c) {
    u64 d;
    asm("fma.rn.f32x2 %0, %1, %2, %3;" : "=l"(d) : "l"(a), "l"(b), "l"(c));
    return d;
}
__device__ __forceinline__ u64 addx2(u64 a, u64 b) {
    u64 d;
    asm("add.rn.f32x2 %0, %1, %2;" : "=l"(d) : "l"(a), "l"(b));
    return d;
}
__device__ __forceinline__ u64 pack2(float a, float b) {
    u64 d;
    asm("mov.b64 %0, {%1, %2};" : "=l"(d) : "f"(a), "f"(b));
    return d;
}
__device__ __forceinline__ u64 dup2(float w) {
    u64 d;
    asm("mov.b64 %0, {%1, %1};" : "=l"(d) : "f"(w));
    return d;
}
__device__ __forceinline__ void f4_to_u64(float4 v, u64& a, u64& b) {
    asm("mov.b64 %0, {%2, %3};\n\tmov.b64 %1, {%4, %5};"
        : "=l"(a), "=l"(b) : "f"(v.x), "f"(v.y), "f"(v.z), "f"(v.w));
}
__device__ __forceinline__ void u64_to_f4(u64 a, u64 b, float4& v) {
    asm("mov.b64 {%0, %1}, %4;\n\tmov.b64 {%2, %3}, %5;"
        : "=f"(v.x), "=f"(v.y), "=f"(v.z), "=f"(v.w) : "l"(a), "l"(b));
}
__device__ __forceinline__ u64 shfl_xor_u64(u64 v, int m) {
    double d = __longlong_as_double((long long)v);
    d = __shfl_xor_sync(0xffffffffu, d, m);
    return (u64)__double_as_longlong(d);
}

// ---------------------------------------------------------------------------
// Kernel 1 (R13 version): q = x@Wt + bh, k = x@Wx. Transposed-W, 2 rows/warp,
// 512 blocks, launch_bounds(256,3).
// ---------------------------------------------------------------------------
__global__ void __launch_bounds__(256, 3) qk_kernel(
    const float* __restrict__ x,
    const float* __restrict__ Wt,
    const float* __restrict__ Wx,
    const float* __restrict__ bh)
{
    __shared__ float xs[8 * F_DIM];                  // 8 rows = 8KB

    const int tid = threadIdx.x;
    const int r0  = blockIdx.x * 8;

    const float4* xg  = reinterpret_cast<const float4*>(x) + (size_t)r0 * F4;
    float4*       xs4 = reinterpret_cast<float4*>(xs);
    xs4[tid]       = xg[tid];
    xs4[tid + 256] = xg[tid + 256];
    __syncthreads();

    const int  wid  = tid >> 5;
    const int  lane = tid & 31;
    const bool is_q = (wid < 4);
    const int  rp   = wid & 3;                       // row pair
    const int  fg   = lane >> 3;                     // f-subgroup 0..3
    const int  u4   = lane & 7;                      // unit quad 0..7

    const float4* __restrict__ Wf4 =
        reinterpret_cast<const float4*>(is_q ? Wt : Wx);   // [F][8 quads]
    const float* xr0 = xs + (2 * rp + 0) * F_DIM;
    const float* xr1 = xs + (2 * rp + 1) * F_DIM;

    u64 a0 = 0ull, b0 = 0ull, a1 = 0ull, b1 = 0ull;

    #pragma unroll 8
    for (int c = 0; c < 64; c++) {                   // lane's f = 4c + fg
        const float4 wv = Wf4[32 * c + lane];        // LDG.128, coalesced
        u64 w01, w23;
        f4_to_u64(wv, w01, w23);
        const u64 xv0 = dup2(xr0[4 * c + fg]);       // LDS.32 broadcast
        const u64 xv1 = dup2(xr1[4 * c + fg]);
        a0 = ffma2(xv0, w01, a0);  b0 = ffma2(xv0, w23, b0);
        a1 = ffma2(xv1, w01, a1);  b1 = ffma2(xv1, w23, b1);
    }

    a0 = addx2(a0, shfl_xor_u64(a0, 8));  a0 = addx2(a0, shfl_xor_u64(a0, 16));
    b0 = addx2(b0, shfl_xor_u64(b0, 8));  b0 = addx2(b0, shfl_xor_u64(b0, 16));
    a1 = addx2(a1, shfl_xor_u64(a1, 8));  a1 = addx2(a1, shfl_xor_u64(a1, 16));
    b1 = addx2(b1, shfl_xor_u64(b1, 8));  b1 = addx2(b1, shfl_xor_u64(b1, 16));

    if (fg < 2) {                                    // fg 0 -> row0, fg 1 -> row1
        const u64 wa = fg ? a1 : a0;
        const u64 wb = fg ? b1 : b0;
        float4 o;
        u64_to_f4(wa, wb, o);
        if (is_q) {
            const float4 bv = reinterpret_cast<const float4*>(bh)[u4];
            o.x += bv.x; o.y += bv.y; o.z += bv.z; o.w += bv.w;
        }
        float4* __restrict__ G4 =
            reinterpret_cast<float4*>(is_q ? g_q : g_k);
        G4[(size_t)(r0 + 2 * rp + fg) * 8 + u4] = o; // STG.128
    }
}

// ---------------------------------------------------------------------------
// Kernel 2 (fused): logits + softmax + v = a @ x for a 16-t tile.
// grid (T/16, B) = 256 blocks, 512 threads (16 warps), all active each phase.
// Phase D: warp = (2-t pair, f-half), LDG.128 x + LDS.64 dup-pair weights
// (the measured-best per-warp shape from R12).
// ---------------------------------------------------------------------------
__global__ void __launch_bounds__(512) attn_out_kernel(
    const float* __restrict__ x,
    const float* __restrict__ Wa,
    const float* __restrict__ ba,
    float* __restrict__ out)
{
    const int b  = blockIdx.y;
    const int t0 = blockIdx.x * TT;
    const int sbase = t0 - HALF;
    const int SR = TT + AW - 1;                  // 79 staged k rows

    __shared__ float ks[79 * 33];                // padded, conflict-free
    __shared__ float qs[TT * UNITS];
    __shared__ float was[UNITS];
    __shared__ float es[TT * AW];
    __shared__ u64   as2[TT * AP];               // dup pairs, zeros at [0],[65]

    const int tid = threadIdx.x;

    for (int idx = tid; idx < SR * UNITS; idx += 512) {
        const int srel = idx >> 5, u = idx & 31;
        int s = sbase + srel;
        s = min(max(s, 0), T_DIM - 1);           // OOB rows masked via es
        ks[srel * 33 + u] = g_k[(size_t)(b * T_DIM + s) * UNITS + u];
    }
    qs[tid] = g_q[(size_t)(b * T_DIM + t0) * UNITS + tid];   // 512 = TT*UNITS
    if (tid < UNITS) was[tid] = Wa[tid];
    __syncthreads();

    // --- logits: 2 per thread (16 t x 64 j = 1024) -------------------------
    #pragma unroll
    for (int l = 0; l < 2; l++) {
        const int idx = tid + l * 512;
        const int tl  = idx >> 6;
        const int j   = idx & 63;
        const int s   = t0 + tl - HALF + j;
        float e = -1e30f;
        if (s >= 0 && s < T_DIM) {
            const int srel = tl + j;
            float acc = 0.f;
            #pragma unroll
            for (int u = 0; u < UNITS; u++)
                acc += was[u] * tanh_approx(qs[tl * UNITS + u] + ks[srel * 33 + u]);
            e = acc + ba[0];
        }
        es[tl * AW + j] = e;
    }
    __syncthreads();

    // --- softmax: 16 warps, one t-row each; zero-padded dup pairs ----------
    const int wid = tid >> 5, lane = tid & 31;
    {
        const float e0 = es[wid * AW + lane];
        const float e1 = es[wid * AW + lane + 32];
        float m = fmaxf(e0, e1);
        #pragma unroll
        for (int o = 16; o; o >>= 1)
            m = fmaxf(m, __shfl_xor_sync(0xffffffffu, m, o));
        const float p0 = __expf(e0 - m);
        const float p1 = __expf(e1 - m);
        float sum = p0 + p1;
        #pragma unroll
        for (int o = 16; o; o >>= 1)
            sum += __shfl_xor_sync(0xffffffffu, sum, o);
        const float inv = 1.f / sum;
        const float a0 = p0 * inv, a1 = p1 * inv;   // exactly 0 when masked
        as2[wid * AP + 1 + lane]  = pack2(a0, a0);
        as2[wid * AP + 33 + lane] = pack2(a1, a1);
        if (lane == 0) {
            as2[wid * AP + 0]      = 0ull;          // pad left
            as2[wid * AP + AW + 1] = 0ull;          // pad right
        }
    }
    __syncthreads();

    // --- phase D: 16 warps = (t-pair 0..7, f-half 0..1) --------------------
    const int p  = wid & 7;                      // t pair: 2p, 2p+1
    const int h  = wid >> 3;                     // f-half
    const int f4 = h * 32 + lane;
    const int ta = t0 + 2 * p;

    const float4* __restrict__ xg4 =
        reinterpret_cast<const float4*>(x) + (size_t)b * T_DIM * F4;
    const u64* awa = as2 + (2 * p + 0) * AP;     // index [1+i]
    const u64* awb = as2 + (2 * p + 1) * AP;     // index [i]

    u64 acc0a = 0ull, acc0b = 0ull, acc1a = 0ull, acc1b = 0ull;

    if (t0 >= HALF && t0 + TT - 1 + HALF < T_DIM) {
        // ---- interior fast path: no clamps, pointer walk ----
        const float4* xp = xg4 + (size_t)(ta - HALF) * F4 + f4;
        #pragma unroll 5
        for (int i = 0; i < AW + 1; i++) {
            u64 xa, xb;
            f4_to_u64(*xp, xa, xb);              // LDG.128
            xp += F4;
            const u64 w0 = awa[i + 1];           // LDS.64 dup pair
            const u64 w1 = awb[i];
            acc0a = ffma2(xa, w0, acc0a);
            acc0b = ffma2(xb, w0, acc0b);
            acc1a = ffma2(xa, w1, acc1a);
            acc1b = ffma2(xb, w1, acc1b);
        }
    } else {
        // ---- boundary path: clamp s; OOB weights are exactly 0 ----
        #pragma unroll 5
        for (int i = 0; i < AW + 1; i++) {
            int s = ta - HALF + i;
            s = min(max(s, 0), T_DIM - 1);
            u64 xa, xb;
            f4_to_u64(xg4[(size_t)s * F4 + f4], xa, xb);
            const u64 w0 = awa[i + 1];
            const u64 w1 = awb[i];
            acc0a = ffma2(xa, w0, acc0a);
            acc0b = ffma2(xb, w0, acc0b);
            acc1a = ffma2(xa, w1, acc1a);
            acc1b = ffma2(xb, w1, acc1b);
        }
    }

    float4 o0, o1;
    u64_to_f4(acc0a, acc0b, o0);
    u64_to_f4(acc1a, acc1b, o1);
    float4* __restrict__ og =
        reinterpret_cast<float4*>(out) + (size_t)b * T_DIM * F4;
    og[(size_t)(ta + 0) * F4 + f4] = o0;
    og[(size_t)(ta + 1) * F4 + f4] = o1;
}

extern "C" void kernel_launch(void* const* d_in, const int* in_sizes, int n_in,
                              void* d_out, int out_size)
{
    const float* x  = (const float*)d_in[0];
    const float* Wt = (const float*)d_in[1];
    const float* Wx = (const float*)d_in[2];
    const float* bh = (const float*)d_in[3];
    const float* Wa = (const float*)d_in[4];
    const float* ba = (const float*)d_in[5];
    float* out = (float*)d_out;

    qk_kernel<<<NROWS / 8, 256>>>(x, Wt, Wx, bh);
    attn_out_kernel<<<dim3(T_DIM / TT, B_DIM), 512>>>(x, Wa, ba, out);
}